// round 15
// baseline (speedup 1.0000x reference)
#include <cuda_runtime.h>
#include <cuda_fp16.h>
#include <cstdint>

#define NTOK   8192
#define HDIM   1024
#define FFDIM  4096
#define NEXP   8
#define NROWS  (NTOK*2)
#define MAXTILES 160               // >= 8 + NROWS/128 = 136
#define GEMM_THREADS 256
#define ROW_BYTES 128              // 64 halves per row, fully packed (BK=64)
#define TILE_A_BYTES (128*ROW_BYTES)   // 16 KB (128 M-rows)
#define TILE_B_BYTES (64*ROW_BYTES)    // 8 KB  (64 N-rows)
#define STAGE_BYTES (TILE_A_BYTES+TILE_B_BYTES)  // 24 KB
#define STAGES 3
#define DYN_SMEM (STAGES*STAGE_BYTES)  // 72 KB -> 3 CTAs/SM

// ------------------------- device scratch (static) ----------------------
__device__ int    g_cnt[NEXP];
__device__ int    g_off[NEXP];
__device__ int    g_topk_e[NTOK*2];
__device__ float  g_topk_w[NTOK*2];
__device__ int    g_rows_token[NROWS];             // row -> token
__device__ int    g_token_row[NTOK*2];             // token,k -> row
__device__ int    g_tile_e[MAXTILES];
__device__ int    g_tile_m0[MAXTILES];
__device__ int    g_tile_valid[MAXTILES];
__device__ int    g_ntiles;
__device__ __half g_w1h[(size_t)NEXP*FFDIM*HDIM];  // fp16+perm16 w1
__device__ __half g_w2h[(size_t)NEXP*HDIM*FFDIM];  // fp16+perm16 w2
__device__ __half g_xh[(size_t)NTOK*HDIM];         // fp16+perm16 x (token order)
__device__ __half g_y1h[(size_t)(NROWS+128)*FFDIM];// fp16+perm16 intermediate
__device__ float  g_out2[(size_t)NROWS*HDIM];      // expert outputs (natural)

// ------------------------- PTX helpers ----------------------------------
__device__ __forceinline__ uint32_t smem_u32(const void* p){
  uint32_t a;
  asm("{ .reg .u64 t; cvta.to.shared.u64 t, %1; cvt.u32.u64 %0, t; }" : "=r"(a) : "l"(p));
  return a;
}
#define CP_ASYNC16(dst, src) \
  asm volatile("cp.async.cg.shared.global [%0], [%1], 16;" :: "r"(dst), "l"(src) : "memory")
#define CP_COMMIT() asm volatile("cp.async.commit_group;" ::: "memory")
#define CP_WAIT(N)  asm volatile("cp.async.wait_group %0;" :: "n"(N) : "memory")
#define LDS64(lo, hi, addr) \
  asm volatile("ld.shared.v2.b32 {%0,%1}, [%2];" : "=r"(lo), "=r"(hi) : "r"(addr))

__device__ __forceinline__ void mma_f16(float& c0, float& c1, float& c2, float& c3,
                                        uint32_t a0, uint32_t a1, uint32_t a2, uint32_t a3,
                                        uint32_t b0, uint32_t b1){
  asm volatile(
    "mma.sync.aligned.m16n8k16.row.col.f32.f16.f16.f32 "
    "{%0,%1,%2,%3}, {%4,%5,%6,%7}, {%8,%9}, {%0,%1,%2,%3};"
    : "+f"(c0), "+f"(c1), "+f"(c2), "+f"(c3)
    : "r"(a0), "r"(a1), "r"(a2), "r"(a3), "r"(b0), "r"(b1));
}
__device__ __forceinline__ float gelu_exact(float v){
  return 0.5f * v * (1.0f + erff(v * 0.70710678118654752f));
}
__device__ __forceinline__ uint32_t h2pack(float a, float b){
  __half2 h = __floats2half2_rn(a, b);
  return *(uint32_t*)&h;
}

// fp16 convert + K-permute one aligned 16-float group:
// pos(8h+2t+b) = 4t+2h+b  (so a thread's k16 fragment = 8 contiguous bytes)
__device__ __forceinline__ void perm16_h(const float4* s4, uint4* d2){
  float4 a = s4[0], b = s4[1], c = s4[2], d = s4[3];
  uint4 o0, o1;
  o0.x = h2pack(a.x, a.y);   // pos 0,1   <- f0,f1
  o0.y = h2pack(c.x, c.y);   // pos 2,3   <- f8,f9
  o0.z = h2pack(a.z, a.w);   // pos 4,5   <- f2,f3
  o0.w = h2pack(c.z, c.w);   // pos 6,7   <- f10,f11
  o1.x = h2pack(b.x, b.y);   // pos 8,9   <- f4,f5
  o1.y = h2pack(d.x, d.y);   // pos 10,11 <- f12,f13
  o1.z = h2pack(b.z, b.w);   // pos 12,13 <- f6,f7
  o1.w = h2pack(d.z, d.w);   // pos 14,15 <- f14,f15
  d2[0] = o0; d2[1] = o1;
}

// ------------------------- prep: BOTH weights fp16+perm16 (+zero cnt) ---
__global__ void __launch_bounds__(256) round_wh_kernel(const float4* __restrict__ s1,
                                                       uint4* __restrict__ d1,
                                                       const float4* __restrict__ s2,
                                                       uint4* __restrict__ d2, int n16){
  if (blockIdx.x == 0 && threadIdx.x < NEXP) g_cnt[threadIdx.x] = 0;
  int i = blockIdx.x * 256 + threadIdx.x;
  const int stride = gridDim.x * 256;
  for (; i < 2 * n16; i += stride) {
    const float4* src = (i < n16) ? s1 : s2;
    uint4*       dst  = (i < n16) ? d1 : d2;
    const int j = (i < n16) ? i : i - n16;
    uint4 o[2];
    perm16_h(src + 4*j, o);
    dst[2*j] = o[0]; dst[2*j+1] = o[1];
  }
}

// ------------------------- router (+ write fp16/perm16 x) ---------------
__global__ void __launch_bounds__(128) moe_router(const float* __restrict__ x,
                                                  const float* __restrict__ rw,
                                                  const float* __restrict__ rb){
  const int lane  = threadIdx.x & 31;
  const int token = blockIdx.x * 4 + (threadIdx.x >> 5);
  const float* xr = x + (size_t)token * HDIM;
  float acc[NEXP];
  #pragma unroll
  for (int e = 0; e < NEXP; ++e) acc[e] = 0.f;
  for (int h = lane; h < HDIM; h += 32) {
    float xv = xr[h];
    #pragma unroll
    for (int e = 0; e < NEXP; ++e) acc[e] += xv * rw[e * HDIM + h];
  }
  #pragma unroll
  for (int e = 0; e < NEXP; ++e) {
    #pragma unroll
    for (int o = 16; o; o >>= 1) acc[e] += __shfl_xor_sync(0xffffffffu, acc[e], o);
  }
  if (lane == 0) {
    float v[NEXP];
    #pragma unroll
    for (int e = 0; e < NEXP; ++e) v[e] = acc[e] + rb[e];
    int e0 = 0; float v0 = v[0];
    #pragma unroll
    for (int e = 1; e < NEXP; ++e) if (v[e] > v0) { v0 = v[e]; e0 = e; }
    int e1 = (e0 == 0) ? 1 : 0; float v1 = v[e1];
    #pragma unroll
    for (int e = 0; e < NEXP; ++e) if (e != e0 && v[e] > v1) { v1 = v[e]; e1 = e; }
    float t  = expf(v1 - v0);
    float w0 = 1.f / (1.f + t);
    g_topk_e[2*token]   = e0;  g_topk_e[2*token+1] = e1;
    g_topk_w[2*token]   = w0;  g_topk_w[2*token+1] = t * w0;
    atomicAdd(&g_cnt[e0], 1);  atomicAdd(&g_cnt[e1], 1);
  }
  // fp16 + perm16 copy of this token's row (64 16-groups, 2 per lane)
  const float4* srcv = (const float4*)xr;
  uint4* dstv = (uint4*)(g_xh + (size_t)token * HDIM);
  #pragma unroll
  for (int j = 0; j < 2; ++j) {
    int gi = lane + 32 * j;
    uint4 o[2];
    perm16_h(srcv + 4*gi, o);
    dstv[2*gi] = o[0]; dstv[2*gi+1] = o[1];
  }
}

// ------------------------- offsets + scatter + tile list ----------------
__global__ void __launch_bounds__(1024) routing_finalize(){
  __shared__ int s_cur[NEXP];
  if (threadIdx.x == 0) {
    int o = 0, nt = 0;
    #pragma unroll
    for (int e = 0; e < NEXP; ++e) {
      g_off[e] = o; s_cur[e] = o;
      const int ce = g_cnt[e];
      for (int mt = 0; mt * 128 < ce; ++mt) {
        g_tile_e[nt]     = e;
        g_tile_m0[nt]    = o + mt * 128;
        g_tile_valid[nt] = min(128, ce - mt * 128);
        ++nt;
      }
      o += ce;
    }
    g_ntiles = nt;
  }
  __syncthreads();
  for (int t = threadIdx.x; t < NTOK; t += 1024) {
    #pragma unroll
    for (int k = 0; k < 2; ++k) {
      int e = g_topk_e[2*t + k];
      int pos = atomicAdd(&s_cur[e], 1);
      g_rows_token[pos]  = t;
      g_token_row[2*t+k] = pos;
    }
  }
}

// ------------------------- unified fp16 m16n8k16 GEMM -------------------
// CTA tile 128(M) x 64(N), BK=64 halves. 8 warps as 4M x 2N, warp tile
// 32x32 -> acc 32 regs/thread -> 3 CTAs/SM (24 warps, latency hiding).
// K stored perm16; smem rows fully packed (64 halves / 128B row); store
// quad cq at phys ((cq+2*(row&3))&7)*16; read 8B slot (4u+tig+4*(g&3))&15.
// FIRST: gather A rows via token list; epilogue gelu + fp16/perm16 out.
template<bool FIRST>
__global__ void __launch_bounds__(GEMM_THREADS, 3)
moe_gemm_h(const __half* __restrict__ A, const __half* __restrict__ W,
           const float* __restrict__ bias, void* __restrict__ outv,
           int Kdim, int Ndim)
{
  const int ti = blockIdx.x;
  if (ti >= g_ntiles) return;
  const int tid  = threadIdx.x;
  const int lane = tid & 31;
  const int wid  = tid >> 5;
  const int e     = g_tile_e[ti];
  const int m0    = g_tile_m0[ti];
  const int valid = g_tile_valid[ti];
  const int n0    = blockIdx.y * 64;

  __shared__ const __half* s_aptr[128];
  extern __shared__ __align__(16) char dsm[];
  const uint32_t dyn0 = smem_u32(dsm);

  if (FIRST && tid < 128) {
    int r   = tid;
    int tok = g_rows_token[m0 + min(r, valid - 1)];
    s_aptr[r] = A + (size_t)tok * Kdim;
  }
  __syncthreads();

  const __half* abase = A + (size_t)m0 * Kdim;          // !FIRST path
  const __half* wbase = W + ((size_t)e * Ndim + n0) * Kdim;
  const int nch = Kdim >> 6;                   // 64 halves per chunk

  const int cr = tid >> 3;                     // base row 0..31
  const int cq = tid & 7;                      // logical 16B quad (0..7)
  const uint32_t dquad = (uint32_t)(((cq + 2*(cr & 3)) & 7) * 16);

  auto issue = [&](int c, uint32_t stoff){
    const uint32_t aS = dyn0 + stoff;
    const uint32_t bS = aS + TILE_A_BYTES;
    const int k0 = c << 6;                     // halves
    #pragma unroll
    for (int j = 0; j < 4; ++j) {              // A: 128 rows
      const int r = cr + 32 * j;               // (r&3)==(cr&3)
      const __half* srcA = FIRST ? (s_aptr[r] + k0 + cq * 8)
                                 : (abase + (size_t)r * Kdim + k0 + cq * 8);
      CP_ASYNC16(aS + (uint32_t)(r * ROW_BYTES) + dquad, srcA);
    }
    #pragma unroll
    for (int j = 0; j < 2; ++j) {              // B: 64 rows
      const int r = cr + 32 * j;
      CP_ASYNC16(bS + (uint32_t)(r * ROW_BYTES) + dquad,
                 wbase + (size_t)r * Kdim + k0 + cq * 8);
    }
  };

  issue(0, 0); CP_COMMIT();
  issue(1, STAGE_BYTES); CP_COMMIT();

  const int wRow = wid >> 1;                   // 0..3 -> M*32
  const int wCol = wid & 1;                    // 0..1 -> N*32
  const int g    = lane >> 2;
  const int tig  = lane & 3;

  // per-k16 8B-slot byte offsets (u = 0..3)
  uint32_t off_u[4];
  #pragma unroll
  for (int u = 0; u < 4; ++u)
    off_u[u] = (uint32_t)((((4*u + tig) + 4*(g & 3)) & 15) * 8);

  const uint32_t awb = dyn0 + (uint32_t)((wRow*32 + g) * ROW_BYTES);
  const uint32_t bwb = dyn0 + TILE_A_BYTES + (uint32_t)((wCol*32 + g) * ROW_BYTES);

  float acc[2][4][4];
  #pragma unroll
  for (int mf = 0; mf < 2; ++mf)
    #pragma unroll
    for (int nf = 0; nf < 4; ++nf)
      #pragma unroll
      for (int q = 0; q < 4; ++q) acc[mf][nf][q] = 0.f;

  uint32_t stoff_c = 0, stoff_n = 2u * STAGE_BYTES;
  for (int c = 0; c < nch; ++c) {
    CP_WAIT(STAGES - 2);
    __syncthreads();
    if (c + STAGES - 1 < nch) issue(c + STAGES - 1, stoff_n);
    CP_COMMIT();

    const uint32_t aw = awb + stoff_c;
    const uint32_t bw = bwb + stoff_c;

    #pragma unroll
    for (int u = 0; u < 4; ++u) {              // four k16 steps per chunk
      const uint32_t au = aw + off_u[u];
      const uint32_t bu = bw + off_u[u];
      uint32_t a0,a1,a2,a3, e0,e1,e2,e3;
      LDS64(a0, a2, au);                       // row wRow*32+g : k-lo, k-hi
      LDS64(a1, a3, au + 8*ROW_BYTES);         // row +8
      LDS64(e0, e2, au + 16*ROW_BYTES);        // mf=1
      LDS64(e1, e3, au + 24*ROW_BYTES);
      #pragma unroll
      for (int nf = 0; nf < 4; ++nf) {
        uint32_t b0, b1;
        LDS64(b0, b1, bu + nf*(8*ROW_BYTES));  // col wCol*32+nf*8+g
        mma_f16(acc[0][nf][0], acc[0][nf][1], acc[0][nf][2], acc[0][nf][3],
                a0, a1, a2, a3, b0, b1);
        mma_f16(acc[1][nf][0], acc[1][nf][1], acc[1][nf][2], acc[1][nf][3],
                e0, e1, e2, e3, b0, b1);
      }
    }
    stoff_c += STAGE_BYTES; if (stoff_c == STAGES*STAGE_BYTES) stoff_c = 0;
    stoff_n += STAGE_BYTES; if (stoff_n == STAGES*STAGE_BYTES) stoff_n = 0;
  }

  // ---------------- epilogue ---------------------------------------------
  const float* bptr = bias + (size_t)e * Ndim + n0;
  #pragma unroll
  for (int mf = 0; mf < 2; ++mf) {
    #pragma unroll
    for (int half = 0; half < 2; ++half) {
      const int rl = wRow * 32 + mf * 16 + g + half * 8;
      if (rl < valid) {
        if (FIRST) {
          // gelu + fp16 round + perm16 scatter:
          // logical cols c0 = wCol*32+nf*8+2tig, c0+1 -> half2 at
          //   (wCol*2 + (nf>>1))*16 + 4*tig + 2*(nf&1)
          __half* orow = (__half*)outv + (size_t)(m0 + rl) * Ndim + n0;
          #pragma unroll
          for (int nf = 0; nf < 4; ++nf) {
            const int nbase = wCol * 32 + nf * 8;
            float v0 = acc[mf][nf][half*2 + 0] + bptr[nbase + 2*tig];
            float v1 = acc[mf][nf][half*2 + 1] + bptr[nbase + 2*tig + 1];
            v0 = gelu_exact(v0); v1 = gelu_exact(v1);
            const int ocol = (wCol*2 + (nf >> 1))*16 + 4*tig + 2*(nf & 1);
            __half2 hv = __floats2half2_rn(v0, v1);
            *(__half2*)(orow + ocol) = hv;
          }
        } else {
          float* orow = (float*)outv + (size_t)(m0 + rl) * Ndim + n0;
          #pragma unroll
          for (int nf = 0; nf < 4; ++nf) {
            const int col = wCol * 32 + nf * 8 + 2*tig;
            float2 v;
            v.x = acc[mf][nf][half*2 + 0] + bptr[col];
            v.y = acc[mf][nf][half*2 + 1] + bptr[col + 1];
            *(float2*)(orow + col) = v;
          }
        }
      }
    }
  }
}

// ------------------------- combine + residual + LN ----------------------
__global__ void __launch_bounds__(256) moe_final_ln(const float* __restrict__ x,
                                                    const float* __restrict__ lnw,
                                                    const float* __restrict__ lnb,
                                                    float* __restrict__ out){
  __shared__ float ps[8], ps2[8], s_mu, s_rs;
  const int t  = blockIdx.x;
  const int r0 = g_token_row[2*t], r1 = g_token_row[2*t+1];
  const float w0 = g_topk_w[2*t],  w1 = g_topk_w[2*t+1];
  const float* xr = x      + (size_t)t  * HDIM;
  const float* a0 = g_out2 + (size_t)r0 * HDIM;
  const float* a1 = g_out2 + (size_t)r1 * HDIM;
  float v[4]; float s = 0.f, s2 = 0.f;
  #pragma unroll
  for (int j = 0; j < 4; ++j) {
    int h = threadIdx.x + 256 * j;
    float val = xr[h] + w0 * a0[h] + w1 * a1[h];
    v[j] = val; s += val; s2 += val * val;
  }
  #pragma unroll
  for (int o = 16; o; o >>= 1) {
    s  += __shfl_xor_sync(0xffffffffu, s,  o);
    s2 += __shfl_xor_sync(0xffffffffu, s2, o);
  }
  const int wd = threadIdx.x >> 5, lane = threadIdx.x & 31;
  if (lane == 0) { ps[wd] = s; ps2[wd] = s2; }
  __syncthreads();
  if (threadIdx.x == 0) {
    float S = 0.f, S2 = 0.f;
    #pragma unroll
    for (int i = 0; i < 8; ++i) { S += ps[i]; S2 += ps2[i]; }
    float mu  = S * (1.f / HDIM);
    float var = S2 * (1.f / HDIM) - mu * mu;
    s_mu = mu; s_rs = rsqrtf(var + 1e-12f);
  }
  __syncthreads();
  const float mu = s_mu, rs = s_rs;
  #pragma unroll
  for (int j = 0; j < 4; ++j) {
    int h = threadIdx.x + 256 * j;
    out[(size_t)t * HDIM + h] = (v[j] - mu) * rs * lnw[h] + lnb[h];
  }
}

// ------------------------- launch ---------------------------------------
extern "C" void kernel_launch(void* const* d_in, const int* in_sizes, int n_in,
                              void* d_out, int out_size){
  (void)in_sizes; (void)n_in; (void)out_size;
  const float* x   = (const float*)d_in[0];
  const float* rw  = (const float*)d_in[1];
  const float* rb  = (const float*)d_in[2];
  const float* w1  = (const float*)d_in[3];
  const float* b1  = (const float*)d_in[4];
  const float* w2  = (const float*)d_in[5];
  const float* b2  = (const float*)d_in[6];
  const float* lnw = (const float*)d_in[7];
  const float* lnb = (const float*)d_in[8];
  float* out = (float*)d_out;

  __half* w1h; cudaGetSymbolAddress((void**)&w1h, g_w1h);
  __half* w2h; cudaGetSymbolAddress((void**)&w2h, g_w2h);
  __half* xhp; cudaGetSymbolAddress((void**)&xhp, g_xh);
  __half* y1p; cudaGetSymbolAddress((void**)&y1p, g_y1h);
  float*  o2p; cudaGetSymbolAddress((void**)&o2p, g_out2);

  cudaFuncSetAttribute(moe_gemm_h<true >, cudaFuncAttributeMaxDynamicSharedMemorySize, DYN_SMEM);
  cudaFuncSetAttribute(moe_gemm_h<false>, cudaFuncAttributeMaxDynamicSharedMemorySize, DYN_SMEM);

  const int N16 = (int)((size_t)NEXP * FFDIM * HDIM / 16);

  round_wh_kernel<<<8192, 256>>>((const float4*)w1, (uint4*)w1h,
                                 (const float4*)w2, (uint4*)w2h, N16);     // 0 (+zero cnt)
  moe_router<<<NTOK/4, 128>>>(x, rw, rb);                                   // 1
  routing_finalize<<<1, 1024>>>();                                         // 2
  moe_gemm_h<true ><<<dim3(144, FFDIM/64), GEMM_THREADS, DYN_SMEM>>>(
      xhp, w1h, b1, y1p, HDIM, FFDIM);                                     // 3: GEMM1 (profiled)
  moe_gemm_h<false><<<dim3(144, HDIM/64), GEMM_THREADS, DYN_SMEM>>>(
      y1p, w2h, b2, o2p, FFDIM, HDIM);                                     // 4: GEMM2
  moe_final_ln<<<NTOK, 256>>>(x, lnw, lnb, out);                           // 5
}

// round 16
// speedup vs baseline: 1.0367x; 1.0367x over previous
#include <cuda_runtime.h>
#include <cuda_fp16.h>
#include <cstdint>

#define NTOK   8192
#define HDIM   1024
#define FFDIM  4096
#define NEXP   8
#define NROWS  (NTOK*2)
#define MAXTILES 160               // >= 8 + NROWS/128 = 136
#define GEMM_THREADS 256
#define ROW_BYTES 128              // 64 halves per row, fully packed (BK=64)
#define TILE_BYTES (128*ROW_BYTES) // 16 KB per operand per stage
#define STAGE_BYTES (2*TILE_BYTES) // 32 KB (A + B)
#define STAGES 3
#define DYN_SMEM (STAGES*STAGE_BYTES)   // 96 KB -> 2 CTAs/SM

#define PREP_BLOCKS 8192
#define ROUTER_BLOCKS (NTOK/8)     // 8 tokens (warps) per 256-thread block

// ------------------------- device scratch (static) ----------------------
__device__ int    g_topk_e[NTOK*2];
__device__ float  g_topk_w[NTOK*2];
__device__ int    g_rows_token[NROWS];             // row -> token
__device__ int    g_token_row[NTOK*2];             // token,k -> row
__device__ int    g_tile_e[MAXTILES];
__device__ int    g_tile_m0[MAXTILES];
__device__ int    g_tile_valid[MAXTILES];
__device__ int    g_ntiles;
__device__ __half g_w1h[(size_t)NEXP*FFDIM*HDIM];  // fp16+perm16 w1
__device__ __half g_w2h[(size_t)NEXP*HDIM*FFDIM];  // fp16+perm16 w2
__device__ __half g_xh[(size_t)NTOK*HDIM];         // fp16+perm16 x (token order)
__device__ __half g_y1h[(size_t)(NROWS+128)*FFDIM];// fp16+perm16 intermediate
__device__ float  g_out2[(size_t)NROWS*HDIM];      // expert outputs (natural)

// ------------------------- PTX helpers ----------------------------------
__device__ __forceinline__ uint32_t smem_u32(const void* p){
  uint32_t a;
  asm("{ .reg .u64 t; cvta.to.shared.u64 t, %1; cvt.u32.u64 %0, t; }" : "=r"(a) : "l"(p));
  return a;
}
#define CP_ASYNC16(dst, src) \
  asm volatile("cp.async.cg.shared.global [%0], [%1], 16;" :: "r"(dst), "l"(src) : "memory")
#define CP_COMMIT() asm volatile("cp.async.commit_group;" ::: "memory")
#define CP_WAIT(N)  asm volatile("cp.async.wait_group %0;" :: "n"(N) : "memory")
#define LDS64(lo, hi, addr) \
  asm volatile("ld.shared.v2.b32 {%0,%1}, [%2];" : "=r"(lo), "=r"(hi) : "r"(addr))

__device__ __forceinline__ void mma_f16(float& c0, float& c1, float& c2, float& c3,
                                        uint32_t a0, uint32_t a1, uint32_t a2, uint32_t a3,
                                        uint32_t b0, uint32_t b1){
  asm volatile(
    "mma.sync.aligned.m16n8k16.row.col.f32.f16.f16.f32 "
    "{%0,%1,%2,%3}, {%4,%5,%6,%7}, {%8,%9}, {%0,%1,%2,%3};"
    : "+f"(c0), "+f"(c1), "+f"(c2), "+f"(c3)
    : "r"(a0), "r"(a1), "r"(a2), "r"(a3), "r"(b0), "r"(b1));
}
__device__ __forceinline__ float gelu_exact(float v){
  return 0.5f * v * (1.0f + erff(v * 0.70710678118654752f));
}
__device__ __forceinline__ uint32_t h2pack(float a, float b){
  __half2 h = __floats2half2_rn(a, b);
  return *(uint32_t*)&h;
}

// fp16 convert + K-permute one aligned 16-float group:
// pos(8h+2t+b) = 4t+2h+b  (so a thread's k16 fragment = 8 contiguous bytes)
__device__ __forceinline__ void perm16_h(const float4* s4, uint4* d2){
  float4 a = s4[0], b = s4[1], c = s4[2], d = s4[3];
  uint4 o0, o1;
  o0.x = h2pack(a.x, a.y);   // pos 0,1   <- f0,f1
  o0.y = h2pack(c.x, c.y);   // pos 2,3   <- f8,f9
  o0.z = h2pack(a.z, a.w);   // pos 4,5   <- f2,f3
  o0.w = h2pack(c.z, c.w);   // pos 6,7   <- f10,f11
  o1.x = h2pack(b.x, b.y);   // pos 8,9   <- f4,f5
  o1.y = h2pack(d.x, d.y);   // pos 10,11 <- f12,f13
  o1.z = h2pack(b.z, b.w);   // pos 12,13 <- f6,f7
  o1.w = h2pack(d.z, d.w);   // pos 14,15 <- f14,f15
  d2[0] = o0; d2[1] = o1;
}

// ------------- merged kernel: weight prep (blocks < PREP_BLOCKS) --------
// -------------              + router       (blocks >= PREP_BLOCKS) ------
__global__ void __launch_bounds__(256)
prep_router(const float* __restrict__ x,
            const float* __restrict__ rw,
            const float* __restrict__ rb,
            const float4* __restrict__ s1, uint4* __restrict__ d1,
            const float4* __restrict__ s2, uint4* __restrict__ d2, int n16){
  if (blockIdx.x < PREP_BLOCKS) {
    // ---- weight conversion path (DRAM-bound streaming) ----
    int i = blockIdx.x * 256 + threadIdx.x;
    const int stride = PREP_BLOCKS * 256;
    for (; i < 2 * n16; i += stride) {
      const float4* src = (i < n16) ? s1 : s2;
      uint4*       dst  = (i < n16) ? d1 : d2;
      const int j = (i < n16) ? i : i - n16;
      uint4 o[2];
      perm16_h(src + 4*j, o);
      dst[2*j] = o[0]; dst[2*j+1] = o[1];
    }
    return;
  }
  // ---- router path: one warp per token (compute-bound) ----
  const int lane  = threadIdx.x & 31;
  const int token = (blockIdx.x - PREP_BLOCKS) * 8 + (threadIdx.x >> 5);
  const float* xr = x + (size_t)token * HDIM;
  float acc[NEXP];
  #pragma unroll
  for (int e = 0; e < NEXP; ++e) acc[e] = 0.f;
  for (int h = lane; h < HDIM; h += 32) {
    float xv = xr[h];
    #pragma unroll
    for (int e = 0; e < NEXP; ++e) acc[e] += xv * rw[e * HDIM + h];
  }
  #pragma unroll
  for (int e = 0; e < NEXP; ++e) {
    #pragma unroll
    for (int o = 16; o; o >>= 1) acc[e] += __shfl_xor_sync(0xffffffffu, acc[e], o);
  }
  if (lane == 0) {
    float v[NEXP];
    #pragma unroll
    for (int e = 0; e < NEXP; ++e) v[e] = acc[e] + rb[e];
    int e0 = 0; float v0 = v[0];
    #pragma unroll
    for (int e = 1; e < NEXP; ++e) if (v[e] > v0) { v0 = v[e]; e0 = e; }
    int e1 = (e0 == 0) ? 1 : 0; float v1 = v[e1];
    #pragma unroll
    for (int e = 0; e < NEXP; ++e) if (e != e0 && v[e] > v1) { v1 = v[e]; e1 = e; }
    float t  = expf(v1 - v0);
    float w0 = 1.f / (1.f + t);
    g_topk_e[2*token]   = e0;  g_topk_e[2*token+1] = e1;
    g_topk_w[2*token]   = w0;  g_topk_w[2*token+1] = t * w0;
  }
  // fp16 + perm16 copy of this token's row (64 16-groups, 2 per lane)
  const float4* srcv = (const float4*)xr;
  uint4* dstv = (uint4*)(g_xh + (size_t)token * HDIM);
  #pragma unroll
  for (int j = 0; j < 2; ++j) {
    int gi = lane + 32 * j;
    uint4 o[2];
    perm16_h(srcv + 4*gi, o);
    dstv[2*gi] = o[0]; dstv[2*gi+1] = o[1];
  }
}

// ----------- histogram + offsets + scatter + tile list (1 block) --------
__global__ void __launch_bounds__(1024) routing_finalize(){
  __shared__ int s_cnt[NEXP];
  __shared__ int s_cur[NEXP];
  if (threadIdx.x < NEXP) s_cnt[threadIdx.x] = 0;
  __syncthreads();
  for (int t = threadIdx.x; t < 2*NTOK; t += 1024)
    atomicAdd(&s_cnt[g_topk_e[t]], 1);
  __syncthreads();
  if (threadIdx.x == 0) {
    int o = 0, nt = 0;
    #pragma unroll
    for (int e = 0; e < NEXP; ++e) {
      s_cur[e] = o;
      const int ce = s_cnt[e];
      for (int mt = 0; mt * 128 < ce; ++mt) {
        g_tile_e[nt]     = e;
        g_tile_m0[nt]    = o + mt * 128;
        g_tile_valid[nt] = min(128, ce - mt * 128);
        ++nt;
      }
      o += ce;
    }
    g_ntiles = nt;
  }
  __syncthreads();
  for (int t = threadIdx.x; t < NTOK; t += 1024) {
    #pragma unroll
    for (int k = 0; k < 2; ++k) {
      int e = g_topk_e[2*t + k];
      int pos = atomicAdd(&s_cur[e], 1);
      g_rows_token[pos]  = t;
      g_token_row[2*t+k] = pos;
    }
  }
}

// ------------------------- unified fp16 m16n8k16 GEMM (R14-proven) ------
// CTA tile 128x128, BK=64 halves, 8 warps 4Mx2N, warp tile 32x64.
// K stored perm16; smem rows fully packed: store quad cq 0..7 at phys
// ((cq+2*(row&3))&7)*16; read 8B slot (4u+tig+4*(g&3))&15, u=0..3.
// FIRST: gather A rows via token list; epilogue gelu + fp16/perm16 out.
template<bool FIRST>
__global__ void __launch_bounds__(GEMM_THREADS, 2)
moe_gemm_h(const __half* __restrict__ A, const __half* __restrict__ W,
           const float* __restrict__ bias, void* __restrict__ outv,
           int Kdim, int Ndim)
{
  const int ti = blockIdx.x;
  if (ti >= g_ntiles) return;
  const int tid  = threadIdx.x;
  const int lane = tid & 31;
  const int wid  = tid >> 5;
  const int e     = g_tile_e[ti];
  const int m0    = g_tile_m0[ti];
  const int valid = g_tile_valid[ti];
  const int n0    = blockIdx.y * 128;

  __shared__ const __half* s_aptr[128];
  extern __shared__ __align__(16) char dsm[];
  const uint32_t dyn0 = smem_u32(dsm);

  if (FIRST && tid < 128) {
    int r   = tid;
    int tok = g_rows_token[m0 + min(r, valid - 1)];
    s_aptr[r] = A + (size_t)tok * Kdim;
  }
  __syncthreads();

  const __half* abase = A + (size_t)m0 * Kdim;          // !FIRST path
  const __half* wbase = W + ((size_t)e * Ndim + n0) * Kdim;
  const int nch = Kdim >> 6;                   // 64 halves per chunk

  const int cr = tid >> 3;                     // base row 0..31
  const int cq = tid & 7;                      // logical 16B quad (0..7)
  const uint32_t dquad = (uint32_t)(((cq + 2*(cr & 3)) & 7) * 16);

  auto issue = [&](int c, uint32_t stoff){
    const uint32_t aS = dyn0 + stoff;
    const uint32_t bS = aS + TILE_BYTES;
    const int k0 = c << 6;                     // halves
    #pragma unroll
    for (int j = 0; j < 4; ++j) {
      const int r = cr + 32 * j;               // (r&3)==(cr&3)
      const __half* srcA = FIRST ? (s_aptr[r] + k0 + cq * 8)
                                 : (abase + (size_t)r * Kdim + k0 + cq * 8);
      CP_ASYNC16(aS + (uint32_t)(r * ROW_BYTES) + dquad, srcA);
      CP_ASYNC16(bS + (uint32_t)(r * ROW_BYTES) + dquad,
                 wbase + (size_t)r * Kdim + k0 + cq * 8);
    }
  };

  issue(0, 0); CP_COMMIT();
  issue(1, STAGE_BYTES); CP_COMMIT();

  const int wRow = wid >> 1;                   // 0..3 -> M*32
  const int wCol = wid & 1;                    // 0..1 -> N*64
  const int g    = lane >> 2;
  const int tig  = lane & 3;

  // per-k16 8B-slot byte offsets (u = 0..3)
  uint32_t off_u[4];
  #pragma unroll
  for (int u = 0; u < 4; ++u)
    off_u[u] = (uint32_t)((((4*u + tig) + 4*(g & 3)) & 15) * 8);

  const uint32_t awb = dyn0 + (uint32_t)((wRow*32 + g) * ROW_BYTES);
  const uint32_t bwb = dyn0 + TILE_BYTES + (uint32_t)((wCol*64 + g) * ROW_BYTES);

  float acc[2][8][4];
  #pragma unroll
  for (int mf = 0; mf < 2; ++mf)
    #pragma unroll
    for (int nf = 0; nf < 8; ++nf)
      #pragma unroll
      for (int q = 0; q < 4; ++q) acc[mf][nf][q] = 0.f;

  uint32_t stoff_c = 0, stoff_n = 2u * STAGE_BYTES;
  for (int c = 0; c < nch; ++c) {
    CP_WAIT(STAGES - 2);
    __syncthreads();
    if (c + STAGES - 1 < nch) issue(c + STAGES - 1, stoff_n);
    CP_COMMIT();

    const uint32_t aw = awb + stoff_c;
    const uint32_t bw = bwb + stoff_c;

    #pragma unroll
    for (int u = 0; u < 4; ++u) {              // four k16 steps per chunk
      const uint32_t au = aw + off_u[u];
      const uint32_t bu = bw + off_u[u];
      uint32_t a0,a1,a2,a3, e0,e1,e2,e3;
      LDS64(a0, a2, au);                       // row wRow*32+g : k-lo, k-hi
      LDS64(a1, a3, au + 8*ROW_BYTES);         // row +8
      LDS64(e0, e2, au + 16*ROW_BYTES);        // mf=1
      LDS64(e1, e3, au + 24*ROW_BYTES);
      #pragma unroll
      for (int nf = 0; nf < 8; ++nf) {
        uint32_t b0, b1;
        LDS64(b0, b1, bu + nf*(8*ROW_BYTES));  // col wCol*64+nf*8+g
        mma_f16(acc[0][nf][0], acc[0][nf][1], acc[0][nf][2], acc[0][nf][3],
                a0, a1, a2, a3, b0, b1);
        mma_f16(acc[1][nf][0], acc[1][nf][1], acc[1][nf][2], acc[1][nf][3],
                e0, e1, e2, e3, b0, b1);
      }
    }
    stoff_c += STAGE_BYTES; if (stoff_c == STAGES*STAGE_BYTES) stoff_c = 0;
    stoff_n += STAGE_BYTES; if (stoff_n == STAGES*STAGE_BYTES) stoff_n = 0;
  }

  // ---------------- epilogue ---------------------------------------------
  const float* bptr = bias + (size_t)e * Ndim + n0;
  #pragma unroll
  for (int mf = 0; mf < 2; ++mf) {
    #pragma unroll
    for (int half = 0; half < 2; ++half) {
      const int rl = wRow * 32 + mf * 16 + g + half * 8;
      if (rl < valid) {
        if (FIRST) {
          // gelu + fp16 round + perm16 scatter:
          // logical cols c0 = wCol*64+nf*8+2tig, c0+1 -> half2 at
          //   (wCol*4 + (nf>>1))*16 + 4*tig + 2*(nf&1)
          __half* orow = (__half*)outv + (size_t)(m0 + rl) * Ndim + n0;
          #pragma unroll
          for (int nf = 0; nf < 8; ++nf) {
            const int nbase = wCol * 64 + nf * 8;
            float v0 = acc[mf][nf][half*2 + 0] + bptr[nbase + 2*tig];
            float v1 = acc[mf][nf][half*2 + 1] + bptr[nbase + 2*tig + 1];
            v0 = gelu_exact(v0); v1 = gelu_exact(v1);
            const int ocol = (wCol*4 + (nf >> 1))*16 + 4*tig + 2*(nf & 1);
            __half2 hv = __floats2half2_rn(v0, v1);
            *(__half2*)(orow + ocol) = hv;
          }
        } else {
          float* orow = (float*)outv + (size_t)(m0 + rl) * Ndim + n0;
          #pragma unroll
          for (int nf = 0; nf < 8; ++nf) {
            const int col = wCol * 64 + nf * 8 + 2*tig;
            float2 v;
            v.x = acc[mf][nf][half*2 + 0] + bptr[col];
            v.y = acc[mf][nf][half*2 + 1] + bptr[col + 1];
            *(float2*)(orow + col) = v;
          }
        }
      }
    }
  }
}

// ------------------------- combine + residual + LN ----------------------
__global__ void __launch_bounds__(256) moe_final_ln(const float* __restrict__ x,
                                                    const float* __restrict__ lnw,
                                                    const float* __restrict__ lnb,
                                                    float* __restrict__ out){
  __shared__ float ps[8], ps2[8], s_mu, s_rs;
  const int t  = blockIdx.x;
  const int r0 = g_token_row[2*t], r1 = g_token_row[2*t+1];
  const float w0 = g_topk_w[2*t],  w1 = g_topk_w[2*t+1];
  const float* xr = x      + (size_t)t  * HDIM;
  const float* a0 = g_out2 + (size_t)r0 * HDIM;
  const float* a1 = g_out2 + (size_t)r1 * HDIM;
  float v[4]; float s = 0.f, s2 = 0.f;
  #pragma unroll
  for (int j = 0; j < 4; ++j) {
    int h = threadIdx.x + 256 * j;
    float val = xr[h] + w0 * a0[h] + w1 * a1[h];
    v[j] = val; s += val; s2 += val * val;
  }
  #pragma unroll
  for (int o = 16; o; o >>= 1) {
    s  += __shfl_xor_sync(0xffffffffu, s,  o);
    s2 += __shfl_xor_sync(0xffffffffu, s2, o);
  }
  const int wd = threadIdx.x >> 5, lane = threadIdx.x & 31;
  if (lane == 0) { ps[wd] = s; ps2[wd] = s2; }
  __syncthreads();
  if (threadIdx.x == 0) {
    float S = 0.f, S2 = 0.f;
    #pragma unroll
    for (int i = 0; i < 8; ++i) { S += ps[i]; S2 += ps2[i]; }
    float mu  = S * (1.f / HDIM);
    float var = S2 * (1.f / HDIM) - mu * mu;
    s_mu = mu; s_rs = rsqrtf(var + 1e-12f);
  }
  __syncthreads();
  const float mu = s_mu, rs = s_rs;
  #pragma unroll
  for (int j = 0; j < 4; ++j) {
    int h = threadIdx.x + 256 * j;
    out[(size_t)t * HDIM + h] = (v[j] - mu) * rs * lnw[h] + lnb[h];
  }
}

// ------------------------- launch ---------------------------------------
extern "C" void kernel_launch(void* const* d_in, const int* in_sizes, int n_in,
                              void* d_out, int out_size){
  (void)in_sizes; (void)n_in; (void)out_size;
  const float* x   = (const float*)d_in[0];
  const float* rw  = (const float*)d_in[1];
  const float* rb  = (const float*)d_in[2];
  const float* w1  = (const float*)d_in[3];
  const float* b1  = (const float*)d_in[4];
  const float* w2  = (const float*)d_in[5];
  const float* b2  = (const float*)d_in[6];
  const float* lnw = (const float*)d_in[7];
  const float* lnb = (const float*)d_in[8];
  float* out = (float*)d_out;

  __half* w1h; cudaGetSymbolAddress((void**)&w1h, g_w1h);
  __half* w2h; cudaGetSymbolAddress((void**)&w2h, g_w2h);
  __half* xhp; cudaGetSymbolAddress((void**)&xhp, g_xh);
  __half* y1p; cudaGetSymbolAddress((void**)&y1p, g_y1h);
  float*  o2p; cudaGetSymbolAddress((void**)&o2p, g_out2);

  cudaFuncSetAttribute(moe_gemm_h<true >, cudaFuncAttributeMaxDynamicSharedMemorySize, DYN_SMEM);
  cudaFuncSetAttribute(moe_gemm_h<false>, cudaFuncAttributeMaxDynamicSharedMemorySize, DYN_SMEM);

  const int N16 = (int)((size_t)NEXP * FFDIM * HDIM / 16);

  prep_router<<<PREP_BLOCKS + ROUTER_BLOCKS, 256>>>(
      x, rw, rb,
      (const float4*)w1, (uint4*)w1h,
      (const float4*)w2, (uint4*)w2h, N16);                                // 0
  routing_finalize<<<1, 1024>>>();                                         // 1
  moe_gemm_h<true ><<<dim3(144, FFDIM/128), GEMM_THREADS, DYN_SMEM>>>(
      xhp, w1h, b1, y1p, HDIM, FFDIM);                                     // 2: GEMM1
  moe_gemm_h<false><<<dim3(144, HDIM/128), GEMM_THREADS, DYN_SMEM>>>(
      y1p, w2h, b2, o2p, FFDIM, HDIM);                                     // 3: GEMM2 (profiled)
  moe_final_ln<<<NTOK, 256>>>(x, lnw, lnb, out);                           // 4
}